// round 3
// baseline (speedup 1.0000x reference)
#include <cuda_runtime.h>
#include <math.h>

#define BB 2
#define TT 2048
#define CC 512
#define NB 4
#define QN (NB*CC)   // 2048
#define HALF (CC/2)  // 256

typedef unsigned long long ull;

// Scratch (no cudaMalloc allowed)
__device__ float g_Q[BB*TT*QN];
__device__ float g_K[BB*TT*CC];
__device__ float g_V[BB*TT*QN];
__device__ float g_Y[BB*TT*CC];

// ---- packed f32x2 helpers ---------------------------------------------------
__device__ __forceinline__ void ffma2(ull &d, ull a, ull b) {
    asm("fma.rn.f32x2 %0, %1, %2, %0;" : "+l"(d) : "l"(a), "l"(b));
}
__device__ __forceinline__ ull fmul2(ull a, ull b) {
    ull r; asm("mul.rn.f32x2 %0, %1, %2;" : "=l"(r) : "l"(a), "l"(b)); return r;
}
__device__ __forceinline__ ull pack2(float x, float y) {
    ull r; asm("mov.b64 %0, {%1, %2};" : "=l"(r) : "f"(x), "f"(y)); return r;
}
__device__ __forceinline__ float2 unpk(ull v) {
    float2 r; asm("mov.b64 {%0, %1}, %2;" : "=f"(r.x), "=f"(r.y) : "l"(v)); return r;
}

// ---------------------------------------------------------------------------
// SGEMM via FFMA2: Out[M,N] = A[M,K] @ W[K,N]. Optional RoPE epilogue + scale.
// BM=128, BN=64, BK=16, 256 threads, 8x4 per thread (as 4 m-pairs x 4 n).
// W tile stored duplicated in smem so FFMA2 operands need no packing.
// ---------------------------------------------------------------------------
template<int DO_ROPE>
__global__ void __launch_bounds__(256) gemm_kernel(
    const float* __restrict__ A, const float* __restrict__ W, float* __restrict__ Out,
    int M, int N, int K,
    const float* __restrict__ cosT, const float* __restrict__ sinT, float scale)
{
    constexpr int BM = 128, BN = 64, BK = 16;
    __shared__ alignas(16) float As[BK][BM];
    __shared__ alignas(16) float Wsd[BK][BN * 2];

    const int tid = threadIdx.x;
    const int tx = tid & 15;
    const int ty = tid >> 4;
    const int rowBase = blockIdx.y * BM;
    const int colBase = blockIdx.x * BN;

    ull acc2[4][4];
#pragma unroll
    for (int mp = 0; mp < 4; mp++)
#pragma unroll
        for (int n = 0; n < 4; n++) acc2[mp][n] = 0ull;

    for (int k0 = 0; k0 < K; k0 += BK) {
        // A tile (128x16) -> transposed smem [k][m]
#pragma unroll
        for (int i = 0; i < 2; i++) {
            int slot = tid + i * 256;
            int r  = slot >> 2;
            int c4 = (slot & 3) * 4;
            float4 v = *(const float4*)(A + (size_t)(rowBase + r) * K + k0 + c4);
            As[c4 + 0][r] = v.x; As[c4 + 1][r] = v.y;
            As[c4 + 2][r] = v.z; As[c4 + 3][r] = v.w;
        }
        // W tile (16x64) -> duplicated pairs [k][2n]=[k][2n+1]=w[n]
        {
            int rr = tid >> 4;
            int c4 = (tid & 15) * 4;
            float4 v = *(const float4*)(W + (size_t)(k0 + rr) * N + colBase + c4);
            float4 d0 = make_float4(v.x, v.x, v.y, v.y);
            float4 d1 = make_float4(v.z, v.z, v.w, v.w);
            *(float4*)&Wsd[rr][2 * c4]     = d0;
            *(float4*)&Wsd[rr][2 * c4 + 4] = d1;
        }
        __syncthreads();

#pragma unroll
        for (int kk = 0; kk < BK; kk++) {
            ulonglong2 a01 = *(ulonglong2*)&As[kk][ty * 8];
            ulonglong2 a23 = *(ulonglong2*)&As[kk][ty * 8 + 4];
            ulonglong2 w01 = *(ulonglong2*)&Wsd[kk][tx * 8];
            ulonglong2 w23 = *(ulonglong2*)&Wsd[kk][tx * 8 + 4];
            ull am[4] = {a01.x, a01.y, a23.x, a23.y};
            ull wn[4] = {w01.x, w01.y, w23.x, w23.y};
#pragma unroll
            for (int mp = 0; mp < 4; mp++)
#pragma unroll
                for (int n = 0; n < 4; n++) ffma2(acc2[mp][n], am[mp], wn[n]);
        }
        __syncthreads();
    }

    const int gc = colBase + tx * 4;
#pragma unroll
    for (int mp = 0; mp < 4; mp++) {
        float2 c0 = unpk(acc2[mp][0]);
        float2 c1 = unpk(acc2[mp][1]);
        float2 c2 = unpk(acc2[mp][2]);
        float2 c3 = unpk(acc2[mp][3]);
        float o[2][4] = {{c0.x, c1.x, c2.x, c3.x}, {c0.y, c1.y, c2.y, c3.y}};
#pragma unroll
        for (int rr2 = 0; rr2 < 2; rr2++) {
            int gr = rowBase + ty * 8 + mp * 2 + rr2;
            float o0 = o[rr2][0], o1 = o[rr2][1], o2 = o[rr2][2], o3 = o[rr2][3];
            if (DO_ROPE) {
                int t   = gr & (TT - 1);
                int cin = gc & (CC - 1);
                int i0  = cin >> 1;
                float c0v = cosT[t * HALF + i0],     s0v = sinT[t * HALF + i0];
                float c1v = cosT[t * HALF + i0 + 1], s1v = sinT[t * HALF + i0 + 1];
                float r0 = o0 * c0v - o1 * s0v;
                float r1 = o0 * s0v + o1 * c0v;
                float r2 = o2 * c1v - o3 * s1v;
                float r3 = o2 * s1v + o3 * c1v;
                o0 = r0; o1 = r1; o2 = r2; o3 = r3;
            }
            *(float4*)(Out + (size_t)gr * N + gc) =
                make_float4(o0 * scale, o1 * scale, o2 * scale, o3 * scale);
        }
    }
}

// ---------------------------------------------------------------------------
// Fused routed attention: 1 warp per query row, 8 rows/CTA, K tile in smem.
// Inner loop batched 4 s-steps: dots via FFMA2, shuffles pipelined, one
// rescale + batched V gather per 4 steps.
// ---------------------------------------------------------------------------
__global__ void __launch_bounds__(256) attn_kernel(
    const float* __restrict__ Q, const float* __restrict__ K,
    const float* __restrict__ V, float* __restrict__ Y)
{
    constexpr int SBLK = 16;
    __shared__ float4 ks[SBLK][CC / 4];   // 32KB

    const int tid  = threadIdx.x;
    const int w    = tid >> 5;
    const int lane = tid & 31;
    const int r    = blockIdx.x * 8 + w;
    const int t    = r & (TT - 1);
    const int tmax = (blockIdx.x * 8 + 7) & (TT - 1);

    // q fragments as f32x2 pairs: q2[n][jj*2], q2[n][jj*2+1]
    ull q2[NB][8];
    {
        const float4* qp4 = (const float4*)(Q + (size_t)r * QN);
#pragma unroll
        for (int n = 0; n < NB; n++)
#pragma unroll
            for (int jj = 0; jj < 4; jj++) {
                float4 v = qp4[n * 128 + jj * 32 + lane];
                ulonglong2 u = *(ulonglong2*)&v;
                q2[n][jj * 2]     = u.x;
                q2[n][jj * 2 + 1] = u.y;
            }
    }

    ull acc2[8];
#pragma unroll
    for (int i = 0; i < 8; i++) acc2[i] = 0ull;
    float m = -1e30f, l = 0.f;

    const float* kb = K + (size_t)(r - t) * CC;
    const float* vb = V + (size_t)(r - t) * QN;

    for (int s0 = 0; s0 <= tmax; s0 += SBLK) {
#pragma unroll
        for (int i = 0; i < 8; i++) {
            int slot = tid + i * 256;
            int si = slot >> 7, cj = slot & 127;
            ks[si][cj] = *(const float4*)(kb + (size_t)(s0 + si) * CC + cj * 4);
        }
        __syncthreads();

        int send = t - s0; if (send > SBLK - 1) send = SBLK - 1;

        for (int si0 = 0; si0 <= send; si0 += 4) {
            float d[4][NB];
            // ---- dots for up to 4 steps (FFMA2) ----
#pragma unroll
            for (int st = 0; st < 4; st++) {
                int si = si0 + st;
                if (si <= send) {
                    ull dd[NB] = {0ull, 0ull, 0ull, 0ull};
#pragma unroll
                    for (int jj = 0; jj < 4; jj++) {
                        float4 kv = ks[si][jj * 32 + lane];
                        ulonglong2 ku = *(ulonglong2*)&kv;
#pragma unroll
                        for (int n = 0; n < NB; n++) {
                            ffma2(dd[n], q2[n][jj * 2],     ku.x);
                            ffma2(dd[n], q2[n][jj * 2 + 1], ku.y);
                        }
                    }
#pragma unroll
                    for (int n = 0; n < NB; n++) {
                        float2 f = unpk(dd[n]);
                        d[st][n] = f.x + f.y;
                    }
                } else {
#pragma unroll
                    for (int n = 0; n < NB; n++) d[st][n] = -1e30f;
                }
            }
            // ---- pipelined warp reduction of 16 independent values ----
#pragma unroll
            for (int off = 16; off > 0; off >>= 1) {
#pragma unroll
                for (int st = 0; st < 4; st++)
#pragma unroll
                    for (int n = 0; n < NB; n++)
                        d[st][n] += __shfl_xor_sync(0xffffffffu, d[st][n], off);
            }
            // ---- branch argmax per step ----
            float smax[4]; int nsel[4];
#pragma unroll
            for (int st = 0; st < 4; st++) {
                float sm = d[st][0]; int ns = 0;
                if (d[st][1] > sm) { sm = d[st][1]; ns = 1; }
                if (d[st][2] > sm) { sm = d[st][2]; ns = 2; }
                if (d[st][3] > sm) { sm = d[st][3]; ns = 3; }
                smax[st] = sm; nsel[st] = ns;
            }
            float mb = fmaxf(fmaxf(smax[0], smax[1]), fmaxf(smax[2], smax[3]));
            float mnew = fmaxf(m, mb);
            float alpha = __expf(m - mnew);
            float p[4];
#pragma unroll
            for (int st = 0; st < 4; st++) p[st] = __expf(smax[st] - mnew);
            l = l * alpha + (p[0] + p[1]) + (p[2] + p[3]);
            m = mnew;

            // ---- rescale + batched V gather/accumulate ----
            ull alpha2 = pack2(alpha, alpha);
#pragma unroll
            for (int i = 0; i < 8; i++) acc2[i] = fmul2(acc2[i], alpha2);
#pragma unroll
            for (int st = 0; st < 4; st++) {
                int si = si0 + st;
                if (si <= send) {
                    ull p2 = pack2(p[st], p[st]);
                    const float4* vr = (const float4*)(vb + (size_t)(s0 + si) * QN + (size_t)nsel[st] * CC);
#pragma unroll
                    for (int jj = 0; jj < 4; jj++) {
                        float4 vv = vr[jj * 32 + lane];
                        ulonglong2 vu = *(ulonglong2*)&vv;
                        ffma2(acc2[jj * 2],     vu.x, p2);
                        ffma2(acc2[jj * 2 + 1], vu.y, p2);
                    }
                }
            }
        }
        __syncthreads();
    }

    float inv = 1.f / l;
    float* yp = Y + (size_t)r * CC;
#pragma unroll
    for (int jj = 0; jj < 4; jj++) {
        float2 a0 = unpk(acc2[jj * 2]);
        float2 a1 = unpk(acc2[jj * 2 + 1]);
        *(float4*)(yp + jj * 128 + lane * 4) =
            make_float4(a0.x * inv, a0.y * inv, a1.x * inv, a1.y * inv);
    }
}

// ---------------------------------------------------------------------------
extern "C" void kernel_launch(void* const* d_in, const int* in_sizes, int n_in,
                              void* d_out, int out_size)
{
    const float* a    = (const float*)d_in[0];
    const float* x    = (const float*)d_in[1];
    const float* Wq   = (const float*)d_in[2];
    const float* Wk   = (const float*)d_in[3];
    const float* Wv   = (const float*)d_in[4];
    const float* Wo   = (const float*)d_in[5];
    const float* cosT = (const float*)d_in[6];
    const float* sinT = (const float*)d_in[7];
    float* out = (float*)d_out;

    float* Qb; cudaGetSymbolAddress((void**)&Qb, g_Q);
    float* Kb; cudaGetSymbolAddress((void**)&Kb, g_K);
    float* Vb; cudaGetSymbolAddress((void**)&Vb, g_V);
    float* Yb; cudaGetSymbolAddress((void**)&Yb, g_Y);

    const int M = BB * TT;
    const float qscale = 0.04419417382415922f;  // 1/sqrt(512)

    dim3 thr(256);
    gemm_kernel<1><<<dim3(QN / 64, M / 128), thr>>>(a, Wq, Qb, M, QN, CC, cosT, sinT, qscale);
    gemm_kernel<1><<<dim3(CC / 64, M / 128), thr>>>(x, Wk, Kb, M, CC, CC, cosT, sinT, 1.0f);
    gemm_kernel<0><<<dim3(QN / 64, M / 128), thr>>>(a, Wv, Vb, M, QN, CC, nullptr, nullptr, 1.0f);
    attn_kernel<<<M / 8, thr>>>(Qb, Kb, Vb, Yb);
    gemm_kernel<0><<<dim3(CC / 64, M / 128), thr>>>(Yb, Wo, out, M, CC, CC, nullptr, nullptr, 1.0f);
}

// round 4
// speedup vs baseline: 1.1389x; 1.1389x over previous
#include <cuda_runtime.h>
#include <math.h>

#define BB 2
#define TT 2048
#define CC 512
#define NB 4
#define QN (NB*CC)   // 2048
#define HALF (CC/2)  // 256

typedef unsigned long long ull;

// Scratch (no cudaMalloc allowed)
__device__ float g_Q[BB*TT*QN];
__device__ float g_K[BB*TT*CC];
__device__ float g_V[BB*TT*QN];
__device__ float g_Y[BB*TT*CC];

// ---- packed f32x2 helpers ---------------------------------------------------
__device__ __forceinline__ void ffma2(ull &d, ull a, ull b) {
    asm("fma.rn.f32x2 %0, %1, %2, %0;" : "+l"(d) : "l"(a), "l"(b));
}
__device__ __forceinline__ float2 unpk(ull v) {
    float2 r; asm("mov.b64 {%0, %1}, %2;" : "=f"(r.x), "=f"(r.y) : "l"(v)); return r;
}

// ---------------------------------------------------------------------------
// SGEMM via FFMA2: Out[M,N] = A[M,K] @ W[K,N]. Optional RoPE epilogue + scale.
// BM=128, BN=64, BK=16, 256 threads, 8x4 per thread (4 m-pairs x 4 n).
// W stored as duplicated f32 pairs split into two 64-float regions per k-row
// so each LDS.128 is 16 lanes x 16B contiguous (conflict-free).
// ---------------------------------------------------------------------------
template<int DO_ROPE>
__global__ void __launch_bounds__(256) gemm_kernel(
    const float* __restrict__ A, const float* __restrict__ W, float* __restrict__ Out,
    int M, int N, int K,
    const float* __restrict__ cosT, const float* __restrict__ sinT, float scale)
{
    constexpr int BM = 128, BN = 64, BK = 16;
    __shared__ alignas(16) float As[BK][BM];
    __shared__ alignas(16) float W0[BK][64];   // pairs for cols (4tx+0, 4tx+1)
    __shared__ alignas(16) float W1[BK][64];   // pairs for cols (4tx+2, 4tx+3)

    const int tid = threadIdx.x;
    const int tx = tid & 15;
    const int ty = tid >> 4;
    const int rowBase = blockIdx.y * BM;
    const int colBase = blockIdx.x * BN;

    ull acc2[4][4];
#pragma unroll
    for (int mp = 0; mp < 4; mp++)
#pragma unroll
        for (int n = 0; n < 4; n++) acc2[mp][n] = 0ull;

    for (int k0 = 0; k0 < K; k0 += BK) {
        // A tile (128x16) -> transposed smem [k][m]
#pragma unroll
        for (int i = 0; i < 2; i++) {
            int slot = tid + i * 256;
            int r  = slot >> 2;
            int c4 = (slot & 3) * 4;
            float4 v = *(const float4*)(A + (size_t)(rowBase + r) * K + k0 + c4);
            As[c4 + 0][r] = v.x; As[c4 + 1][r] = v.y;
            As[c4 + 2][r] = v.z; As[c4 + 3][r] = v.w;
        }
        // W tile (16x64) -> duplicated pairs, two contiguous regions
        {
            int rr  = tid >> 4;
            int txw = tid & 15;
            float4 v = *(const float4*)(W + (size_t)(k0 + rr) * N + colBase + txw * 4);
            *(float4*)&W0[rr][txw * 4] = make_float4(v.x, v.x, v.y, v.y);
            *(float4*)&W1[rr][txw * 4] = make_float4(v.z, v.z, v.w, v.w);
        }
        __syncthreads();

#pragma unroll
        for (int kk = 0; kk < BK; kk++) {
            ulonglong2 a01 = *(ulonglong2*)&As[kk][ty * 8];
            ulonglong2 a23 = *(ulonglong2*)&As[kk][ty * 8 + 4];
            ulonglong2 w01 = *(ulonglong2*)&W0[kk][tx * 4];
            ulonglong2 w23 = *(ulonglong2*)&W1[kk][tx * 4];
            ull am[4] = {a01.x, a01.y, a23.x, a23.y};
            ull wn[4] = {w01.x, w01.y, w23.x, w23.y};
#pragma unroll
            for (int mp = 0; mp < 4; mp++)
#pragma unroll
                for (int n = 0; n < 4; n++) ffma2(acc2[mp][n], am[mp], wn[n]);
        }
        __syncthreads();
    }

    const int gc = colBase + tx * 4;
#pragma unroll
    for (int mp = 0; mp < 4; mp++) {
        float2 c0 = unpk(acc2[mp][0]);
        float2 c1 = unpk(acc2[mp][1]);
        float2 c2 = unpk(acc2[mp][2]);
        float2 c3 = unpk(acc2[mp][3]);
        float o[2][4] = {{c0.x, c1.x, c2.x, c3.x}, {c0.y, c1.y, c2.y, c3.y}};
#pragma unroll
        for (int rr2 = 0; rr2 < 2; rr2++) {
            int gr = rowBase + ty * 8 + mp * 2 + rr2;
            float o0 = o[rr2][0], o1 = o[rr2][1], o2 = o[rr2][2], o3 = o[rr2][3];
            if (DO_ROPE) {
                int t   = gr & (TT - 1);
                int cin = gc & (CC - 1);
                int i0  = cin >> 1;
                float c0v = cosT[t * HALF + i0],     s0v = sinT[t * HALF + i0];
                float c1v = cosT[t * HALF + i0 + 1], s1v = sinT[t * HALF + i0 + 1];
                float r0 = o0 * c0v - o1 * s0v;
                float r1 = o0 * s0v + o1 * c0v;
                float r2 = o2 * c1v - o3 * s1v;
                float r3 = o2 * s1v + o3 * c1v;
                o0 = r0; o1 = r1; o2 = r2; o3 = r3;
            }
            *(float4*)(Out + (size_t)gr * N + gc) =
                make_float4(o0 * scale, o1 * scale, o2 * scale, o3 * scale);
        }
    }
}

// ---------------------------------------------------------------------------
// Fused routed attention (R1 version, known-good): 1 warp per query row,
// 8 rows/CTA, K tile in smem, online softmax with branch argmax, V gathered.
// ---------------------------------------------------------------------------
__global__ void __launch_bounds__(256) attn_kernel(
    const float* __restrict__ Q, const float* __restrict__ K,
    const float* __restrict__ V, float* __restrict__ Y)
{
    constexpr int SBLK = 16;
    __shared__ float4 ks[SBLK][CC / 4];   // 32KB

    const int tid  = threadIdx.x;
    const int w    = tid >> 5;
    const int lane = tid & 31;
    const int r    = blockIdx.x * 8 + w;
    const int t    = r & (TT - 1);
    const int tmax = (blockIdx.x * 8 + 7) & (TT - 1);

    float4 q[NB][4];
    const float* qp = Q + (size_t)r * QN;
#pragma unroll
    for (int n = 0; n < NB; n++)
#pragma unroll
        for (int jj = 0; jj < 4; jj++)
            q[n][jj] = *(const float4*)(qp + n * CC + jj * 128 + lane * 4);

    float4 acc[4];
#pragma unroll
    for (int jj = 0; jj < 4; jj++) acc[jj] = make_float4(0.f, 0.f, 0.f, 0.f);
    float m = -1e30f, l = 0.f;

    const float* kb = K + (size_t)(r - t) * CC;
    const float* vb = V + (size_t)(r - t) * QN;

    for (int s0 = 0; s0 <= tmax; s0 += SBLK) {
#pragma unroll
        for (int i = 0; i < 8; i++) {
            int slot = tid + i * 256;
            int si = slot >> 7, cj = slot & 127;
            ks[si][cj] = *(const float4*)(kb + (size_t)(s0 + si) * CC + cj * 4);
        }
        __syncthreads();

        int send = t - s0; if (send > SBLK - 1) send = SBLK - 1;
        for (int si = 0; si <= send; si++) {
            float4 k4[4];
#pragma unroll
            for (int jj = 0; jj < 4; jj++) k4[jj] = ks[si][jj * 32 + lane];

            float d[NB];
#pragma unroll
            for (int n = 0; n < NB; n++) {
                float s = 0.f;
#pragma unroll
                for (int jj = 0; jj < 4; jj++) {
                    s += q[n][jj].x * k4[jj].x;
                    s += q[n][jj].y * k4[jj].y;
                    s += q[n][jj].z * k4[jj].z;
                    s += q[n][jj].w * k4[jj].w;
                }
                d[n] = s;
            }
#pragma unroll
            for (int off = 16; off > 0; off >>= 1) {
#pragma unroll
                for (int n = 0; n < NB; n++)
                    d[n] += __shfl_xor_sync(0xffffffffu, d[n], off);
            }

            float smax = d[0]; int nsel = 0;
            if (d[1] > smax) { smax = d[1]; nsel = 1; }
            if (d[2] > smax) { smax = d[2]; nsel = 2; }
            if (d[3] > smax) { smax = d[3]; nsel = 3; }

            float mnew  = fmaxf(m, smax);
            float alpha = __expf(m - mnew);
            float p     = __expf(smax - mnew);
            l = l * alpha + p;

            const float4* vr = (const float4*)(vb + (size_t)(s0 + si) * QN + (size_t)nsel * CC);
#pragma unroll
            for (int jj = 0; jj < 4; jj++) {
                float4 vv = vr[jj * 32 + lane];
                acc[jj].x = acc[jj].x * alpha + p * vv.x;
                acc[jj].y = acc[jj].y * alpha + p * vv.y;
                acc[jj].z = acc[jj].z * alpha + p * vv.z;
                acc[jj].w = acc[jj].w * alpha + p * vv.w;
            }
            m = mnew;
        }
        __syncthreads();
    }

    float inv = 1.f / l;
    float* yp = Y + (size_t)r * CC;
#pragma unroll
    for (int jj = 0; jj < 4; jj++) {
        float4 o = make_float4(acc[jj].x * inv, acc[jj].y * inv,
                               acc[jj].z * inv, acc[jj].w * inv);
        *(float4*)(yp + jj * 128 + lane * 4) = o;
    }
}

// ---------------------------------------------------------------------------
extern "C" void kernel_launch(void* const* d_in, const int* in_sizes, int n_in,
                              void* d_out, int out_size)
{
    const float* a    = (const float*)d_in[0];
    const float* x    = (const float*)d_in[1];
    const float* Wq   = (const float*)d_in[2];
    const float* Wk   = (const float*)d_in[3];
    const float* Wv   = (const float*)d_in[4];
    const float* Wo   = (const float*)d_in[5];
    const float* cosT = (const float*)d_in[6];
    const float* sinT = (const float*)d_in[7];
    float* out = (float*)d_out;

    float* Qb; cudaGetSymbolAddress((void**)&Qb, g_Q);
    float* Kb; cudaGetSymbolAddress((void**)&Kb, g_K);
    float* Vb; cudaGetSymbolAddress((void**)&Vb, g_V);
    float* Yb; cudaGetSymbolAddress((void**)&Yb, g_Y);

    const int M = BB * TT;
    const float qscale = 0.04419417382415922f;  // 1/sqrt(512)

    dim3 thr(256);
    gemm_kernel<1><<<dim3(QN / 64, M / 128), thr>>>(a, Wq, Qb, M, QN, CC, cosT, sinT, qscale);
    gemm_kernel<1><<<dim3(CC / 64, M / 128), thr>>>(x, Wk, Kb, M, CC, CC, cosT, sinT, 1.0f);
    gemm_kernel<0><<<dim3(QN / 64, M / 128), thr>>>(a, Wv, Vb, M, QN, CC, nullptr, nullptr, 1.0f);
    attn_kernel<<<M / 8, thr>>>(Qb, Kb, Vb, Yb);
    gemm_kernel<0><<<dim3(CC / 64, M / 128), thr>>>(Yb, Wo, out, M, CC, CC, nullptr, nullptr, 1.0f);
}